// round 16
// baseline (speedup 1.0000x reference)
#include <cuda_runtime.h>
#include <math.h>

#define NN 50000
#define NE 800000
#define KF 128          // IN_F
#define HF 128          // HEADS * OUT_F
#define NH 4
#define OF 32
#define EF 32
#define NBLK 196        // ceil(NN/256)
#define SST 136         // smem row stride in words (conflict-free fragments)

// ---------------- scratch (device globals: allocation-free) ----------------
__device__ float g_ht[(size_t)NN * HF];                 // 25.6 MB
__device__ __align__(16) float g_ai[NN * NH];
__device__ __align__(16) float g_aj[NN * NH];
__device__ __align__(16) float g_s[(size_t)NE * NH];    // raw scores, ROW-SORTED
__device__ int   g_col[NE];                             // sorted -> col
__device__ int   g_eid[NE];                             // sorted -> edge id
__device__ int   g_cnt[NN];
__device__ int   g_pre[NN];
__device__ int   g_off[NN];
__device__ int   g_pos[NN];
__device__ int   g_bsum[NBLK];
__device__ __align__(16) float g_wv[8 * KF];            // [q][k]: q<4 = W·a_i, q>=4 = W·a_j
__device__ __align__(16) float g_vct[EF * NH];          // transposed: [k][head]
__device__ __align__(16) float g_c4[NH];                // bias term per head
__device__ unsigned int g_maxbits;

__device__ __forceinline__ unsigned f2o(float x) {
    unsigned u = __float_as_uint(x);
    return (u & 0x80000000u) ? ~u : (u | 0x80000000u);
}
__device__ __forceinline__ float o2f(unsigned u) {
    return __uint_as_float((u & 0x80000000u) ? (u & 0x7fffffffu) : ~u);
}

// split float into tf32 hi + tf32 lo (3xTF32 trick)
__device__ __forceinline__ void tf32split(float x, unsigned& hi, unsigned& lo) {
    asm("cvt.rna.tf32.f32 %0, %1;" : "=r"(hi) : "f"(x));
    float l = x - __uint_as_float(hi);
    asm("cvt.rna.tf32.f32 %0, %1;" : "=r"(lo) : "f"(l));
}

__device__ __forceinline__ void mma_tf32(float* c, const unsigned* a,
                                         unsigned b0, unsigned b1) {
    asm volatile(
        "mma.sync.aligned.m16n8k8.row.col.f32.tf32.tf32.f32 "
        "{%0,%1,%2,%3}, {%4,%5,%6,%7}, {%8,%9}, {%0,%1,%2,%3};"
        : "+f"(c[0]), "+f"(c[1]), "+f"(c[2]), "+f"(c[3])
        : "r"(a[0]), "r"(a[1]), "r"(a[2]), "r"(a[3]), "r"(b0), "r"(b1));
}

// ---------------- kernel 0: init (wvec, vct, c4, maxbits) ------------------
__global__ void k_init(const float* __restrict__ eW, const float* __restrict__ a,
                       const float* __restrict__ eb, const float* __restrict__ W) {
    int t = threadIdx.x;
    if (blockIdx.x == 0) {
        // wvec[q][k] = sum_f W[k, head*32+f] * a[head*96 + (q>=4?32:0) + f]
        int q = t >> 7;          // 0..7
        int k = t & 127;
        int hh = q & 3;
        int off = hh * 96 + ((q >= 4) ? 32 : 0);
        float s = 0.0f;
        #pragma unroll
        for (int f = 0; f < OF; f++)
            s += W[(size_t)k * HF + hh * OF + f] * a[off + f];
        g_wv[q * KF + k] = s;
    } else {
        if (t < EF * NH) {       // vct[k][h] = sum_f eW[k, h*32+f] * a_e[h][f]
            int k = t >> 2, hh = t & 3;
            float s = 0.0f;
            #pragma unroll
            for (int f = 0; f < OF; f++)
                s += eW[k * HF + hh * OF + f] * a[hh * 96 + 64 + f];
            g_vct[t] = s;
        } else if (t < EF * NH + NH) {
            int hh = t - EF * NH;
            float s = 0.0f;
            #pragma unroll
            for (int f = 0; f < OF; f++)
                s += eb[hh * OF + f] * a[hh * 96 + 64 + f];
            g_c4[hh] = s;
        } else if (t == EF * NH + NH) {
            g_maxbits = 0u;
        }
    }
}

// ---------------- kernel 0b: alpha_i/alpha_j = h @ wvec (warp per node) ----
__global__ __launch_bounds__(256) void k_alpha(const float* __restrict__ h) {
    __shared__ float swv[8][KF];          // [q][k]
    int t = threadIdx.x;
    for (int i = t; i < 8 * KF; i += 256)
        ((float*)swv)[i] = g_wv[i];
    __syncthreads();
    int w = t >> 5, lane = t & 31;
    int n = blockIdx.x * 8 + w;           // grid = NN/8 exactly
    float4 hv = *(const float4*)(h + (size_t)n * KF + lane * 4);
    float p[8];
    #pragma unroll
    for (int q = 0; q < 8; q++) {
        float4 wv = *(const float4*)&swv[q][lane * 4];   // LDS.128, conflict-free
        p[q] = hv.x * wv.x + hv.y * wv.y + hv.z * wv.z + hv.w * wv.w;
    }
    #pragma unroll
    for (int o = 16; o; o >>= 1) {
        #pragma unroll
        for (int q = 0; q < 8; q++)
            p[q] += __shfl_xor_sync(0xffffffffu, p[q], o);
    }
    if (lane == 0) {
        *(float4*)(g_ai + (size_t)n * 4) = make_float4(p[0], p[1], p[2], p[3]);
        *(float4*)(g_aj + (size_t)n * 4) = make_float4(p[4], p[5], p[6], p[7]);
    }
}

// ---------------- kernel 1: row histogram ----------------------------------
__global__ __launch_bounds__(256) void k_count(const int* __restrict__ ei) {
    int e = blockIdx.x * blockDim.x + threadIdx.x;
    if (e < NE) atomicAdd(&g_cnt[ei[e]], 1);
}

// ---------------- scan stage 1 ---------------------------------------------
__global__ __launch_bounds__(256) void k_scan1() {
    __shared__ int sh[256];
    int t = threadIdx.x;
    int i = blockIdx.x * 256 + t;
    int c = (i < NN) ? g_cnt[i] : 0;
    sh[t] = c;
    __syncthreads();
    #pragma unroll
    for (int o = 1; o < 256; o <<= 1) {
        int v = (t >= o) ? sh[t - o] : 0;
        __syncthreads();
        sh[t] += v;
        __syncthreads();
    }
    if (i < NN) g_pre[i] = sh[t] - c;
    if (t == 255) g_bsum[blockIdx.x] = sh[255];
}

// ---------------- scan stage 2+3 merged ------------------------------------
__global__ __launch_bounds__(256) void k_scan23() {
    __shared__ int sh[256];
    int t = threadIdx.x;
    sh[t] = (t < blockIdx.x) ? g_bsum[t] : 0;   // NBLK <= 256
    __syncthreads();
    #pragma unroll
    for (int o = 128; o; o >>= 1) {
        if (t < o) sh[t] += sh[t + o];
        __syncthreads();
    }
    int base = sh[0];
    int i = blockIdx.x * 256 + t;
    if (i < NN) {
        int o = g_pre[i] + base;
        g_off[i] = o;
        g_pos[i] = o;
    }
}

// ---------------- kernel 2: ht = h @ W via 3xTF32 mma ----------------------
__global__ __launch_bounds__(256) void k_gemm(const float* __restrict__ h,
                                              const float* __restrict__ W) {
    __shared__ unsigned As_hi[8 * SST], As_lo[8 * SST];
    __shared__ unsigned Bs_hi[8 * SST], Bs_lo[8 * SST];
    int row0 = blockIdx.x * 128;
    int t = threadIdx.x;
    int lane = t & 31;
    int wid = t >> 5;
    int wm = wid >> 1;          // 0..3 M-group
    int wn = wid & 1;           // 0..1 N-group

    int lr = t >> 1;            // A-load row 0..127
    int lk = (t & 1) * 4;       // A-load k offset 0/4
    int bk = t >> 5;            // B-load k row 0..7
    int bc = (t & 31) * 4;      // B-load col 0..124

    float acc[2][8][4];
    #pragma unroll
    for (int mt = 0; mt < 2; mt++)
        #pragma unroll
        for (int nt = 0; nt < 8; nt++)
            #pragma unroll
            for (int q = 0; q < 4; q++) acc[mt][nt][q] = 0.0f;

    for (int k0 = 0; k0 < KF; k0 += 8) {    // 16 iterations, rolled
        {
            float4 hv = make_float4(0.f, 0.f, 0.f, 0.f);
            if (row0 + lr < NN)
                hv = *(const float4*)(h + (size_t)(row0 + lr) * KF + k0 + lk);
            unsigned hi, lo;
            tf32split(hv.x, hi, lo); As_hi[(lk+0)*SST + lr] = hi; As_lo[(lk+0)*SST + lr] = lo;
            tf32split(hv.y, hi, lo); As_hi[(lk+1)*SST + lr] = hi; As_lo[(lk+1)*SST + lr] = lo;
            tf32split(hv.z, hi, lo); As_hi[(lk+2)*SST + lr] = hi; As_lo[(lk+2)*SST + lr] = lo;
            tf32split(hv.w, hi, lo); As_hi[(lk+3)*SST + lr] = hi; As_lo[(lk+3)*SST + lr] = lo;
            float4 wv = *(const float4*)(W + (size_t)(k0 + bk) * HF + bc);
            unsigned h0,l0,h1,l1,h2,l2,h3,l3;
            tf32split(wv.x, h0, l0); tf32split(wv.y, h1, l1);
            tf32split(wv.z, h2, l2); tf32split(wv.w, h3, l3);
            *(uint4*)(Bs_hi + bk*SST + bc) = make_uint4(h0, h1, h2, h3);
            *(uint4*)(Bs_lo + bk*SST + bc) = make_uint4(l0, l1, l2, l3);
        }
        __syncthreads();

        int r = lane >> 2, ck = lane & 3;
        unsigned ah[2][4], al[2][4];
        #pragma unroll
        for (int mt = 0; mt < 2; mt++) {
            int rr = wm * 32 + mt * 16 + r;
            ah[mt][0] = As_hi[ck*SST + rr];       ah[mt][1] = As_hi[ck*SST + rr + 8];
            ah[mt][2] = As_hi[(ck+4)*SST + rr];   ah[mt][3] = As_hi[(ck+4)*SST + rr + 8];
            al[mt][0] = As_lo[ck*SST + rr];       al[mt][1] = As_lo[ck*SST + rr + 8];
            al[mt][2] = As_lo[(ck+4)*SST + rr];   al[mt][3] = As_lo[(ck+4)*SST + rr + 8];
        }
        #pragma unroll
        for (int nt = 0; nt < 8; nt++) {
            int nn = wn * 64 + nt * 8 + (lane >> 2);
            unsigned bh0 = Bs_hi[ck*SST + nn], bh1 = Bs_hi[(ck+4)*SST + nn];
            unsigned bl0 = Bs_lo[ck*SST + nn], bl1 = Bs_lo[(ck+4)*SST + nn];
            #pragma unroll
            for (int mt = 0; mt < 2; mt++) {
                mma_tf32(acc[mt][nt], ah[mt], bh0, bh1);
                mma_tf32(acc[mt][nt], ah[mt], bl0, bl1);
                mma_tf32(acc[mt][nt], al[mt], bh0, bh1);
            }
        }
        __syncthreads();
    }

    // epilogue: store ht
    {
        int r = lane >> 2;
        int c2 = (lane & 3) * 2;
        #pragma unroll
        for (int mt = 0; mt < 2; mt++) {
            int grow0 = row0 + wm * 32 + mt * 16 + r;
            int grow1 = grow0 + 8;
            #pragma unroll
            for (int nt = 0; nt < 8; nt++) {
                int col = wn * 64 + nt * 8 + c2;
                if (grow0 < NN)
                    *(float2*)(g_ht + (size_t)grow0 * HF + col) =
                        make_float2(acc[mt][nt][0], acc[mt][nt][1]);
                if (grow1 < NN)
                    *(float2*)(g_ht + (size_t)grow1 * HF + col) =
                        make_float2(acc[mt][nt][2], acc[mt][nt][3]);
            }
        }
    }
}

// ---------------- kernel 3: edge scores + global max + ticketed place ------
__global__ __launch_bounds__(256) void k_edge(const int* __restrict__ ei,
                                              const float* __restrict__ ea) {
    __shared__ float4 svct[EF];
    __shared__ float4 sc4;
    if (threadIdx.x < EF) svct[threadIdx.x] = *(const float4*)(g_vct + threadIdx.x * 4);
    if (threadIdx.x == EF) sc4 = *(const float4*)g_c4;
    __syncthreads();

    int e = blockIdx.x * blockDim.x + threadIdx.x;
    float m = -1e30f;
    if (e < NE) {
        int row = ei[e];
        int col = ei[NE + e];
        float4 s4 = sc4;
        #pragma unroll
        for (int q = 0; q < 8; q++) {
            float4 x = *(const float4*)(ea + (size_t)e * EF + q * 4);
            float4 v0 = svct[q * 4 + 0];
            float4 v1 = svct[q * 4 + 1];
            float4 v2 = svct[q * 4 + 2];
            float4 v3 = svct[q * 4 + 3];
            s4.x += x.x * v0.x + x.y * v1.x + x.z * v2.x + x.w * v3.x;
            s4.y += x.x * v0.y + x.y * v1.y + x.z * v2.y + x.w * v3.y;
            s4.z += x.x * v0.z + x.y * v1.z + x.z * v2.z + x.w * v3.z;
            s4.w += x.x * v0.w + x.y * v1.w + x.z * v2.w + x.w * v3.w;
        }
        float4 ai = *(const float4*)(g_ai + (size_t)row * NH);
        float4 aj = *(const float4*)(g_aj + (size_t)col * NH);
        s4.x += ai.x + aj.x; s4.y += ai.y + aj.y;
        s4.z += ai.z + aj.z; s4.w += ai.w + aj.w;
        s4.x = (s4.x > 0.f) ? s4.x : 0.2f * s4.x;
        s4.y = (s4.y > 0.f) ? s4.y : 0.2f * s4.y;
        s4.z = (s4.z > 0.f) ? s4.z : 0.2f * s4.z;
        s4.w = (s4.w > 0.f) ? s4.w : 0.2f * s4.w;
        int p = atomicAdd(&g_pos[row], 1);
        *(float4*)(g_s + (size_t)p * NH) = s4;
        g_col[p] = col;
        g_eid[p] = e;
        m = fmaxf(fmaxf(s4.x, s4.y), fmaxf(s4.z, s4.w));
    }
    #pragma unroll
    for (int o = 16; o; o >>= 1) m = fmaxf(m, __shfl_xor_sync(0xffffffffu, m, o));
    __shared__ float smax[8];
    if ((threadIdx.x & 31) == 0) smax[threadIdx.x >> 5] = m;
    __syncthreads();
    if (threadIdx.x == 0) {
        float bm = smax[0];
        #pragma unroll
        for (int w = 1; w < 8; w++) bm = fmaxf(bm, smax[w]);
        atomicMax(&g_maxbits, f2o(bm));
    }
}

// ---------------- kernel 4: warp-per-node gather (denom, att, h_out, elu) --
__global__ __launch_bounds__(128) void k_nodes(float* __restrict__ out_h,
                                               float* __restrict__ out_att) {
    __shared__ float s_att[4][32][4];
    __shared__ int   s_col[4][32];
    int w = threadIdx.x >> 5;
    int n = blockIdx.x * 4 + w;            // grid = NN/4 exactly
    int lane = threadIdx.x & 31;
    int start = g_off[n];
    int cnt = g_cnt[n];
    float M = o2f(g_maxbits);

    float s = 0.0f;
    const float* sbase = g_s + (size_t)start * 4;
    for (int i = lane; i < cnt * 4; i += 32) s += __expf(sbase[i] - M);
    s += __shfl_xor_sync(0xffffffffu, s, 4);
    s += __shfl_xor_sync(0xffffffffu, s, 8);
    s += __shfl_xor_sync(0xffffffffu, s, 16);
    float inv_h = 1.0f / (s + 1e-8f);                      // head = lane&3
    float i0 = __shfl_sync(0xffffffffu, inv_h, 0);
    float i1 = __shfl_sync(0xffffffffu, inv_h, 1);
    float i2 = __shfl_sync(0xffffffffu, inv_h, 2);
    float i3 = __shfl_sync(0xffffffffu, inv_h, 3);

    int myhead = lane >> 3;
    float4 acc = make_float4(0.f, 0.f, 0.f, 0.f);
    for (int k0 = 0; k0 < cnt; k0 += 32) {
        int k = k0 + lane;
        if (k < cnt) {
            size_t idx = (size_t)(start + k);
            float4 sr = *(const float4*)(g_s + idx * 4);
            float4 at = make_float4(__expf(sr.x - M) * i0, __expf(sr.y - M) * i1,
                                    __expf(sr.z - M) * i2, __expf(sr.w - M) * i3);
            *(float4*)(out_att + (size_t)g_eid[idx] * 4) = at;
            *(float4*)(&s_att[w][lane][0]) = at;
            s_col[w][lane] = g_col[idx];
        }
        __syncwarp();
        int lim = min(32, cnt - k0);
        #pragma unroll 4
        for (int j = 0; j < lim; j++) {
            int col  = s_col[w][j];
            float wt = s_att[w][j][myhead];
            float4 x = *(const float4*)(g_ht + (size_t)col * HF + lane * 4);
            acc.x += wt * x.x; acc.y += wt * x.y;
            acc.z += wt * x.z; acc.w += wt * x.w;
        }
        __syncwarp();
    }
    acc.x = (acc.x > 0.f) ? acc.x : expm1f(acc.x);
    acc.y = (acc.y > 0.f) ? acc.y : expm1f(acc.y);
    acc.z = (acc.z > 0.f) ? acc.z : expm1f(acc.z);
    acc.w = (acc.w > 0.f) ? acc.w : expm1f(acc.w);
    *(float4*)(out_h + (size_t)n * HF + lane * 4) = acc;
}

// ---------------- launcher: GEMM-decoupled forked graph --------------------
extern "C" void kernel_launch(void* const* d_in, const int* in_sizes, int n_in,
                              void* d_out, int out_size) {
    (void)in_sizes; (void)n_in; (void)out_size;
    const float* h  = (const float*)d_in[0];
    const int*   ei = (const int*)d_in[1];
    const float* ea = (const float*)d_in[2];
    const float* W  = (const float*)d_in[3];
    const float* a  = (const float*)d_in[4];
    const float* eW = (const float*)d_in[5];
    const float* eb = (const float*)d_in[6];

    float* out_h   = (float*)d_out;                       // [NN, 128]
    float* out_att = (float*)d_out + (size_t)NN * HF;     // [NE, 4]

    void* cnt_ptr = 0;
    cudaGetSymbolAddress(&cnt_ptr, g_cnt);

    cudaStream_t s2;
    cudaStreamCreateWithFlags(&s2, cudaStreamNonBlocking);
    cudaEvent_t evFork, evJoin;
    cudaEventCreateWithFlags(&evFork, cudaEventDisableTiming);
    cudaEventCreateWithFlags(&evJoin, cudaEventDisableTiming);

    // fork; ENTIRE attention-prep chain (incl. edge scores) on s2 —
    // it no longer depends on the GEMM (alpha = h @ (W·a))
    cudaEventRecord(evFork, 0);
    cudaStreamWaitEvent(s2, evFork, 0);
    cudaMemsetAsync(cnt_ptr, 0, NN * sizeof(int), s2);
    k_init<<<2, 1024, 0, s2>>>(eW, a, eb, W);
    k_alpha<<<NN / 8, 256, 0, s2>>>(h);
    k_count<<<(NE + 255) / 256, 256, 0, s2>>>(ei);
    k_scan1<<<NBLK, 256, 0, s2>>>();
    k_scan23<<<NBLK, 256, 0, s2>>>();
    k_edge<<<(NE + 255) / 256, 256, 0, s2>>>(ei, ea);
    cudaEventRecord(evJoin, s2);

    // main stream: gemm (writes g_ht only)
    k_gemm<<<(NN + 127) / 128, 256>>>(h, W);

    // join: nodes needs g_ht (main) + sorted scores/max (s2)
    cudaStreamWaitEvent(0, evJoin, 0);
    k_nodes<<<NN / 4, 128>>>(out_h, out_att);

    cudaEventDestroy(evFork);
    cudaEventDestroy(evJoin);
    cudaStreamDestroy(s2);
}

// round 17
// speedup vs baseline: 1.7640x; 1.7640x over previous
#include <cuda_runtime.h>
#include <cuda_fp16.h>
#include <math.h>

#define NN 50000
#define NE 800000
#define KF 128          // IN_F
#define HF 128          // HEADS * OUT_F
#define NH 4
#define OF 32
#define EF 32
#define NBLK 196        // ceil(NN/256)
#define SST 136         // smem row stride in words (conflict-free fragments)

// ---------------- scratch (device globals: allocation-free) ----------------
__device__ __half g_hth[(size_t)NN * HF];               // 12.8 MB (fp16 ht)
__device__ __align__(16) float g_ai[NN * NH];
__device__ __align__(16) float g_aj[NN * NH];
__device__ __align__(16) float g_s[(size_t)NE * NH];    // raw scores, ROW-SORTED
__device__ int   g_col[NE];                             // sorted -> col
__device__ int   g_eid[NE];                             // sorted -> edge id
__device__ int   g_cnt[NN];
__device__ int   g_pre[NN];
__device__ int   g_off[NN];
__device__ int   g_pos[NN];
__device__ int   g_bsum[NBLK];
__device__ __align__(16) float g_vct[EF * NH];          // transposed: [k][head]
__device__ __align__(16) float g_c4[NH];                // bias term per head
__device__ unsigned int g_maxbits;

__device__ __forceinline__ unsigned f2o(float x) {
    unsigned u = __float_as_uint(x);
    return (u & 0x80000000u) ? ~u : (u | 0x80000000u);
}
__device__ __forceinline__ float o2f(unsigned u) {
    return __uint_as_float((u & 0x80000000u) ? (u & 0x7fffffffu) : ~u);
}

// split float into tf32 hi + tf32 lo (3xTF32 trick)
__device__ __forceinline__ void tf32split(float x, unsigned& hi, unsigned& lo) {
    asm("cvt.rna.tf32.f32 %0, %1;" : "=r"(hi) : "f"(x));
    float l = x - __uint_as_float(hi);
    asm("cvt.rna.tf32.f32 %0, %1;" : "=r"(lo) : "f"(l));
}

__device__ __forceinline__ void mma_tf32(float* c, const unsigned* a,
                                         unsigned b0, unsigned b1) {
    asm volatile(
        "mma.sync.aligned.m16n8k8.row.col.f32.tf32.tf32.f32 "
        "{%0,%1,%2,%3}, {%4,%5,%6,%7}, {%8,%9}, {%0,%1,%2,%3};"
        : "+f"(c[0]), "+f"(c[1]), "+f"(c[2]), "+f"(c[3])
        : "r"(a[0]), "r"(a[1]), "r"(a[2]), "r"(a[3]), "r"(b0), "r"(b1));
}

// ---------------- kernel 0: init (vct transposed, c, reset max) ------------
__global__ void k_init(const float* __restrict__ eW, const float* __restrict__ a,
                       const float* __restrict__ eb) {
    int t = threadIdx.x;
    if (t < EF * NH) {
        int k = t >> 2, h = t & 3;
        float s = 0.0f;
        #pragma unroll
        for (int f = 0; f < OF; f++)
            s += eW[k * HF + h * OF + f] * a[h * 96 + 64 + f];
        g_vct[t] = s;
    } else if (t < EF * NH + NH) {
        int h = t - EF * NH;
        float s = 0.0f;
        #pragma unroll
        for (int f = 0; f < OF; f++)
            s += eb[h * OF + f] * a[h * 96 + 64 + f];
        g_c4[h] = s;
    } else if (t == EF * NH + NH) {
        g_maxbits = 0u;
    }
}

// ---------------- kernel 1: row histogram ----------------------------------
__global__ __launch_bounds__(256) void k_count(const int* __restrict__ ei) {
    int e = blockIdx.x * blockDim.x + threadIdx.x;
    if (e < NE) atomicAdd(&g_cnt[ei[e]], 1);
}

// ---------------- scan stage 1 ---------------------------------------------
__global__ __launch_bounds__(256) void k_scan1() {
    __shared__ int sh[256];
    int t = threadIdx.x;
    int i = blockIdx.x * 256 + t;
    int c = (i < NN) ? g_cnt[i] : 0;
    sh[t] = c;
    __syncthreads();
    #pragma unroll
    for (int o = 1; o < 256; o <<= 1) {
        int v = (t >= o) ? sh[t - o] : 0;
        __syncthreads();
        sh[t] += v;
        __syncthreads();
    }
    if (i < NN) g_pre[i] = sh[t] - c;
    if (t == 255) g_bsum[blockIdx.x] = sh[255];
}

// ---------------- scan stage 2+3 merged ------------------------------------
__global__ __launch_bounds__(256) void k_scan23() {
    __shared__ int sh[256];
    int t = threadIdx.x;
    sh[t] = (t < blockIdx.x) ? g_bsum[t] : 0;   // NBLK <= 256
    __syncthreads();
    #pragma unroll
    for (int o = 128; o; o >>= 1) {
        if (t < o) sh[t] += sh[t + o];
        __syncthreads();
    }
    int base = sh[0];
    int i = blockIdx.x * 256 + t;
    if (i < NN) {
        int o = g_pre[i] + base;
        g_off[i] = o;
        g_pos[i] = o;
    }
}

// ---------------- kernel 2: ht = h @ W via 3xTF32 mma, fused alpha ---------
__global__ __launch_bounds__(256) void k_gemm(const float* __restrict__ h,
                                              const float* __restrict__ W,
                                              const float* __restrict__ a) {
    __shared__ unsigned As_hi[8 * SST], As_lo[8 * SST];
    __shared__ unsigned Bs_hi[8 * SST], Bs_lo[8 * SST];
    __shared__ float s_ai[512];
    __shared__ float s_aj[512];
    int row0 = blockIdx.x * 128;
    int t = threadIdx.x;
    int lane = t & 31;
    int wid = t >> 5;
    int wm = wid >> 1;          // 0..3 M-group
    int wn = wid & 1;           // 0..1 N-group
    s_ai[t] = 0.0f; s_ai[t + 256] = 0.0f;
    s_aj[t] = 0.0f; s_aj[t + 256] = 0.0f;

    int lr = t >> 1;            // A-load row 0..127
    int lk = (t & 1) * 4;       // A-load k offset 0/4
    int bk = t >> 5;            // B-load k row 0..7
    int bc = (t & 31) * 4;      // B-load col 0..124

    float acc[2][8][4];
    #pragma unroll
    for (int mt = 0; mt < 2; mt++)
        #pragma unroll
        for (int nt = 0; nt < 8; nt++)
            #pragma unroll
            for (int q = 0; q < 4; q++) acc[mt][nt][q] = 0.0f;

    for (int k0 = 0; k0 < KF; k0 += 8) {    // 16 iterations, rolled
        {
            float4 hv = make_float4(0.f, 0.f, 0.f, 0.f);
            if (row0 + lr < NN)
                hv = *(const float4*)(h + (size_t)(row0 + lr) * KF + k0 + lk);
            unsigned hi, lo;
            tf32split(hv.x, hi, lo); As_hi[(lk+0)*SST + lr] = hi; As_lo[(lk+0)*SST + lr] = lo;
            tf32split(hv.y, hi, lo); As_hi[(lk+1)*SST + lr] = hi; As_lo[(lk+1)*SST + lr] = lo;
            tf32split(hv.z, hi, lo); As_hi[(lk+2)*SST + lr] = hi; As_lo[(lk+2)*SST + lr] = lo;
            tf32split(hv.w, hi, lo); As_hi[(lk+3)*SST + lr] = hi; As_lo[(lk+3)*SST + lr] = lo;
            float4 wv = *(const float4*)(W + (size_t)(k0 + bk) * HF + bc);
            unsigned h0,l0,h1,l1,h2,l2,h3,l3;
            tf32split(wv.x, h0, l0); tf32split(wv.y, h1, l1);
            tf32split(wv.z, h2, l2); tf32split(wv.w, h3, l3);
            *(uint4*)(Bs_hi + bk*SST + bc) = make_uint4(h0, h1, h2, h3);
            *(uint4*)(Bs_lo + bk*SST + bc) = make_uint4(l0, l1, l2, l3);
        }
        __syncthreads();

        int r = lane >> 2, ck = lane & 3;
        unsigned ah[2][4], al[2][4];
        #pragma unroll
        for (int mt = 0; mt < 2; mt++) {
            int rr = wm * 32 + mt * 16 + r;
            ah[mt][0] = As_hi[ck*SST + rr];       ah[mt][1] = As_hi[ck*SST + rr + 8];
            ah[mt][2] = As_hi[(ck+4)*SST + rr];   ah[mt][3] = As_hi[(ck+4)*SST + rr + 8];
            al[mt][0] = As_lo[ck*SST + rr];       al[mt][1] = As_lo[ck*SST + rr + 8];
            al[mt][2] = As_lo[(ck+4)*SST + rr];   al[mt][3] = As_lo[(ck+4)*SST + rr + 8];
        }
        #pragma unroll
        for (int nt = 0; nt < 8; nt++) {
            int nn = wn * 64 + nt * 8 + (lane >> 2);
            unsigned bh0 = Bs_hi[ck*SST + nn], bh1 = Bs_hi[(ck+4)*SST + nn];
            unsigned bl0 = Bs_lo[ck*SST + nn], bl1 = Bs_lo[(ck+4)*SST + nn];
            #pragma unroll
            for (int mt = 0; mt < 2; mt++) {
                mma_tf32(acc[mt][nt], ah[mt], bh0, bh1);
                mma_tf32(acc[mt][nt], ah[mt], bl0, bl1);
                mma_tf32(acc[mt][nt], al[mt], bh0, bh1);
            }
        }
        __syncthreads();
    }

    // epilogue: store ht (fp16) + fused alpha_i/alpha_j (f32 accs)
    {
        int r = lane >> 2;
        int c2 = (lane & 3) * 2;
        #pragma unroll
        for (int mt = 0; mt < 2; mt++) {
            int lrow0 = wm * 32 + mt * 16 + r;
            int lrow1 = lrow0 + 8;
            int grow0 = row0 + lrow0;
            int grow1 = row0 + lrow1;
            float pi0[2] = {0.f, 0.f}, pj0[2] = {0.f, 0.f};
            float pi1[2] = {0.f, 0.f}, pj1[2] = {0.f, 0.f};
            #pragma unroll
            for (int nt = 0; nt < 8; nt++) {
                int col = wn * 64 + nt * 8 + c2;
                int hh = col >> 5;
                int cm = col & 31;
                float wia = __ldg(&a[hh * 96 + cm]);
                float wib = __ldg(&a[hh * 96 + cm + 1]);
                float wja = __ldg(&a[hh * 96 + 32 + cm]);
                float wjb = __ldg(&a[hh * 96 + 32 + cm + 1]);
                int hl = nt >> 2;
                pi0[hl] += acc[mt][nt][0] * wia + acc[mt][nt][1] * wib;
                pj0[hl] += acc[mt][nt][0] * wja + acc[mt][nt][1] * wjb;
                pi1[hl] += acc[mt][nt][2] * wia + acc[mt][nt][3] * wib;
                pj1[hl] += acc[mt][nt][2] * wja + acc[mt][nt][3] * wjb;
                if (grow0 < NN)
                    *(__half2*)(g_hth + (size_t)grow0 * HF + col) =
                        __floats2half2_rn(acc[mt][nt][0], acc[mt][nt][1]);
                if (grow1 < NN)
                    *(__half2*)(g_hth + (size_t)grow1 * HF + col) =
                        __floats2half2_rn(acc[mt][nt][2], acc[mt][nt][3]);
            }
            #pragma unroll
            for (int hl = 0; hl < 2; hl++) {
                int hh = wn * 2 + hl;
                atomicAdd(&s_ai[lrow0 * 4 + hh], pi0[hl]);
                atomicAdd(&s_aj[lrow0 * 4 + hh], pj0[hl]);
                atomicAdd(&s_ai[lrow1 * 4 + hh], pi1[hl]);
                atomicAdd(&s_aj[lrow1 * 4 + hh], pj1[hl]);
            }
        }
    }
    __syncthreads();
    #pragma unroll
    for (int s = 0; s < 2; s++) {
        int u = t + s * 256;
        int r = row0 + (u >> 2);
        if (r < NN) {
            g_ai[r * 4 + (u & 3)] = s_ai[u];
            g_aj[r * 4 + (u & 3)] = s_aj[u];
        }
    }
}

// ---------------- kernel 3: edge scores + global max + ticketed place ------
__global__ __launch_bounds__(256) void k_edge(const int* __restrict__ ei,
                                              const float* __restrict__ ea) {
    __shared__ float4 svct[EF];
    __shared__ float4 sc4;
    if (threadIdx.x < EF) svct[threadIdx.x] = *(const float4*)(g_vct + threadIdx.x * 4);
    if (threadIdx.x == EF) sc4 = *(const float4*)g_c4;
    __syncthreads();

    int e = blockIdx.x * blockDim.x + threadIdx.x;
    float m = -1e30f;
    if (e < NE) {
        int row = ei[e];
        int col = ei[NE + e];
        float4 s4 = sc4;
        #pragma unroll
        for (int q = 0; q < 8; q++) {
            float4 x = *(const float4*)(ea + (size_t)e * EF + q * 4);
            float4 v0 = svct[q * 4 + 0];
            float4 v1 = svct[q * 4 + 1];
            float4 v2 = svct[q * 4 + 2];
            float4 v3 = svct[q * 4 + 3];
            s4.x += x.x * v0.x + x.y * v1.x + x.z * v2.x + x.w * v3.x;
            s4.y += x.x * v0.y + x.y * v1.y + x.z * v2.y + x.w * v3.y;
            s4.z += x.x * v0.z + x.y * v1.z + x.z * v2.z + x.w * v3.z;
            s4.w += x.x * v0.w + x.y * v1.w + x.z * v2.w + x.w * v3.w;
        }
        float4 ai = *(const float4*)(g_ai + (size_t)row * NH);
        float4 aj = *(const float4*)(g_aj + (size_t)col * NH);
        s4.x += ai.x + aj.x; s4.y += ai.y + aj.y;
        s4.z += ai.z + aj.z; s4.w += ai.w + aj.w;
        s4.x = (s4.x > 0.f) ? s4.x : 0.2f * s4.x;
        s4.y = (s4.y > 0.f) ? s4.y : 0.2f * s4.y;
        s4.z = (s4.z > 0.f) ? s4.z : 0.2f * s4.z;
        s4.w = (s4.w > 0.f) ? s4.w : 0.2f * s4.w;
        int p = atomicAdd(&g_pos[row], 1);
        *(float4*)(g_s + (size_t)p * NH) = s4;
        g_col[p] = col;
        g_eid[p] = e;
        m = fmaxf(fmaxf(s4.x, s4.y), fmaxf(s4.z, s4.w));
    }
    #pragma unroll
    for (int o = 16; o; o >>= 1) m = fmaxf(m, __shfl_xor_sync(0xffffffffu, m, o));
    __shared__ float smax[8];
    if ((threadIdx.x & 31) == 0) smax[threadIdx.x >> 5] = m;
    __syncthreads();
    if (threadIdx.x == 0) {
        float bm = smax[0];
        #pragma unroll
        for (int w = 1; w < 8; w++) bm = fmaxf(bm, smax[w]);
        atomicMax(&g_maxbits, f2o(bm));
    }
}

// ---------------- kernel 4: warp-per-node gather (denom, att, h_out, elu) --
__global__ __launch_bounds__(128) void k_nodes(float* __restrict__ out_h,
                                               float* __restrict__ out_att) {
    __shared__ float s_att[4][32][4];
    __shared__ int   s_col[4][32];
    int w = threadIdx.x >> 5;
    int n = blockIdx.x * 4 + w;            // grid = NN/4 exactly
    int lane = threadIdx.x & 31;
    int start = g_off[n];
    int cnt = g_cnt[n];
    float M = o2f(g_maxbits);

    float s = 0.0f;
    const float* sbase = g_s + (size_t)start * 4;
    for (int i = lane; i < cnt * 4; i += 32) s += __expf(sbase[i] - M);
    s += __shfl_xor_sync(0xffffffffu, s, 4);
    s += __shfl_xor_sync(0xffffffffu, s, 8);
    s += __shfl_xor_sync(0xffffffffu, s, 16);
    float inv_h = 1.0f / (s + 1e-8f);                      // head = lane&3
    float i0 = __shfl_sync(0xffffffffu, inv_h, 0);
    float i1 = __shfl_sync(0xffffffffu, inv_h, 1);
    float i2 = __shfl_sync(0xffffffffu, inv_h, 2);
    float i3 = __shfl_sync(0xffffffffu, inv_h, 3);

    int myhead = lane >> 3;
    float4 acc = make_float4(0.f, 0.f, 0.f, 0.f);
    for (int k0 = 0; k0 < cnt; k0 += 32) {
        int k = k0 + lane;
        if (k < cnt) {
            size_t idx = (size_t)(start + k);
            float4 sr = *(const float4*)(g_s + idx * 4);
            float4 at = make_float4(__expf(sr.x - M) * i0, __expf(sr.y - M) * i1,
                                    __expf(sr.z - M) * i2, __expf(sr.w - M) * i3);
            *(float4*)(out_att + (size_t)g_eid[idx] * 4) = at;
            *(float4*)(&s_att[w][lane][0]) = at;
            s_col[w][lane] = g_col[idx];
        }
        __syncwarp();
        int lim = min(32, cnt - k0);
        #pragma unroll 4
        for (int j = 0; j < lim; j++) {
            int col  = s_col[w][j];
            float wt = s_att[w][j][myhead];
            uint2 u = *(const uint2*)(g_hth + (size_t)col * HF + lane * 4);
            float2 x01 = __half22float2(*reinterpret_cast<__half2*>(&u.x));
            float2 x23 = __half22float2(*reinterpret_cast<__half2*>(&u.y));
            acc.x += wt * x01.x; acc.y += wt * x01.y;
            acc.z += wt * x23.x; acc.w += wt * x23.y;
        }
        __syncwarp();
    }
    acc.x = (acc.x > 0.f) ? acc.x : expm1f(acc.x);
    acc.y = (acc.y > 0.f) ? acc.y : expm1f(acc.y);
    acc.z = (acc.z > 0.f) ? acc.z : expm1f(acc.z);
    acc.w = (acc.w > 0.f) ? acc.w : expm1f(acc.w);
    *(float4*)(out_h + (size_t)n * HF + lane * 4) = acc;
}

// ---------------- launcher: forked-capture graph (R13 structure) -----------
extern "C" void kernel_launch(void* const* d_in, const int* in_sizes, int n_in,
                              void* d_out, int out_size) {
    (void)in_sizes; (void)n_in; (void)out_size;
    const float* h  = (const float*)d_in[0];
    const int*   ei = (const int*)d_in[1];
    const float* ea = (const float*)d_in[2];
    const float* W  = (const float*)d_in[3];
    const float* a  = (const float*)d_in[4];
    const float* eW = (const float*)d_in[5];
    const float* eb = (const float*)d_in[6];

    float* out_h   = (float*)d_out;                       // [NN, 128]
    float* out_att = (float*)d_out + (size_t)NN * HF;     // [NE, 4]

    void* cnt_ptr = 0;
    cudaGetSymbolAddress(&cnt_ptr, g_cnt);

    cudaStream_t s2;
    cudaStreamCreateWithFlags(&s2, cudaStreamNonBlocking);
    cudaEvent_t evFork, evJoin;
    cudaEventCreateWithFlags(&evFork, cudaEventDisableTiming);
    cudaEventCreateWithFlags(&evJoin, cudaEventDisableTiming);

    // branch A (side stream): init + histogram + scans
    cudaMemsetAsync(cnt_ptr, 0, NN * sizeof(int), 0);
    cudaEventRecord(evFork, 0);
    cudaStreamWaitEvent(s2, evFork, 0);
    k_init<<<1, 160, 0, s2>>>(eW, a, eb);
    k_count<<<(NE + 255) / 256, 256, 0, s2>>>(ei);
    k_scan1<<<NBLK, 256, 0, s2>>>();
    k_scan23<<<NBLK, 256, 0, s2>>>();
    cudaEventRecord(evJoin, s2);

    // branch B (main stream): gemm (depends only on h, W, a)
    k_gemm<<<(NN + 127) / 128, 256>>>(h, W, a);

    // join: edge needs g_pos/g_off/g_vct (A) and g_ai/g_aj (B)
    cudaStreamWaitEvent(0, evJoin, 0);
    k_edge<<<(NE + 255) / 256, 256>>>(ei, ea);
    k_nodes<<<NN / 4, 128>>>(out_h, out_att);

    cudaEventDestroy(evFork);
    cudaEventDestroy(evJoin);
    cudaStreamDestroy(s2);
}